// round 16
// baseline (speedup 1.0000x reference)
#include <cuda_runtime.h>
#include <math.h>

namespace {
constexpr int    Bn = 32, Cn = 32, Ln = 16384, WIN = 64, HOP = 32;
constexpr int    NF = 511, ND = 33;
constexpr double PEN = 5.0;
constexpr int    MAXSEG = 520, MAXTOK = 4608, ANCH = 16;
constexpr double PI_D = 3.14159265358979323846264338327950288;
constexpr int    SEGBUF = 1024;
constexpr int    PELT_DBL  = 16896 + 512 + 512 + 512 + 512;
constexpr size_t PELT_SMEM = PELT_DBL * 8 + (512 + 514) * 2 + 16;
}

// ------------------------------- scratch ----------------------------------
__device__ float  g_x[Bn][Cn][Ln];
__device__ float  g_sig[Bn][Ln];
__device__ double g_feats[Bn][NF][ND];
__device__ double g_cs [Bn][NF + 1][ND];
__device__ double g_cs2[Bn][NF + 1][ND];
__device__ double g_s2 [Bn][NF + 1];
__device__ int    g_nseg[Bn];
__device__ int    g_seg_s[Bn][MAXSEG];
__device__ int    g_seg_e[Bn][MAXSEG];
__device__ int    g_seg_off[Bn][MAXSEG];
__device__ double g_spec[Bn][Ln / 2 + 8];
__device__ double g_dp[Bn][MAXSEG];
__device__ double g_bwv[Bn][MAXSEG];
__device__ int    g_pl[Bn][MAXSEG];
__device__ int    g_ntok[Bn];
__device__ int    g_tok_s[Bn][MAXTOK];
__device__ int    g_tok_e[Bn][MAXTOK];
__device__ int    g_tok_seg[Bn][MAXTOK];

// precomputed constants
__device__ float2 c_tw_re[WIN], c_tw_im[WIN], c_win[WIN];
__device__ float2 c_c32[17];
__device__ float2 c_lnc[11];
__device__ float2 c_ln2;
__device__ float2 c_eps;
__device__ double c_recip[NF + 1];

// ---------------------------- double-single ops ----------------------------
struct DS { float hi, lo; };
__device__ __forceinline__ DS two_sum(float a, float b) {
    float s = a + b, bb = s - a;
    float e = (a - (s - bb)) + (b - bb);
    return {s, e};
}
__device__ __forceinline__ DS quick2(float a, float b) {
    float s = a + b;
    return {s, b - (s - a)};
}
__device__ __forceinline__ DS ds_add(DS a, DS b) {
    DS s = two_sum(a.hi, b.hi);
    return quick2(s.hi, s.lo + a.lo + b.lo);
}
__device__ __forceinline__ DS ds_mul(DS a, DS b) {
    float p = a.hi * b.hi;
    float e = fmaf(a.hi, b.hi, -p);
    e = fmaf(a.hi, b.lo, e);
    e = fmaf(a.lo, b.hi, e);
    return quick2(p, e);
}
__device__ __forceinline__ DS ds_neg(DS a) { return {-a.hi, -a.lo}; }
__device__ __forceinline__ DS ds_from_d(double v) {
    float hi = (float)v;
    return {hi, (float)(v - (double)hi)};
}

// DS natural log; v > 0 well inside float range. abs err ~1e-13.
__device__ DS ds_log(DS v) {
    int e;
    float mh = frexpf(v.hi, &e);
    if (mh < 0.7071067811865476f) e -= 1;
    float sc = ldexpf(1.0f, -e);
    DS m = {v.hi * sc, v.lo * sc};
    DS num = ds_add(m, {-1.0f, 0.0f});
    DS den = ds_add(m, { 1.0f, 0.0f});
    float r = 1.0f / den.hi;
    float q1 = num.hi * r;
    DS t  = ds_add(num, ds_neg(ds_mul(den, {q1, 0.f})));
    float q2 = t.hi * r;
    DS t2 = ds_add(t,  ds_neg(ds_mul(den, {q2, 0.f})));
    float q3 = t2.hi * r;
    DS z = ds_add(ds_add({q1, 0.f}, {q2, 0.f}), {q3, 0.f});
    DS w = ds_mul(z, z);
    DS p = {c_lnc[10].x, c_lnc[10].y};
    #pragma unroll
    for (int k = 9; k >= 0; --k)
        p = ds_add(ds_mul(p, w), {c_lnc[k].x, c_lnc[k].y});
    DS lnm = ds_mul(ds_mul({2.0f, 0.f}, z), p);
    return ds_add(ds_mul({(float)e, 0.f}, {c_ln2.x, c_ln2.y}), lnm);
}

// numpy pairwise sum (float32), exact replication
__device__ float np_pairwise_sum(const float* a, int n) {
    if (n < 8) {
        float r = 0.0f;
        for (int i = 0; i < n; ++i) r += a[i];
        return r;
    } else if (n <= 128) {
        float r[8];
        #pragma unroll
        for (int j = 0; j < 8; ++j) r[j] = a[j];
        int i = 8;
        for (; i < n - (n % 8); i += 8) {
            #pragma unroll
            for (int j = 0; j < 8; ++j) r[j] += a[i + j];
        }
        float res = ((r[0] + r[1]) + (r[2] + r[3])) + ((r[4] + r[5]) + (r[6] + r[7]));
        for (; i < n; ++i) res += a[i];
        return res;
    } else {
        int n2 = n / 2;
        n2 -= n2 % 8;
        return np_pairwise_sum(a, n2) + np_pairwise_sum(a + n2, n - n2);
    }
}

// ---- 1) stage x -> g_x + channel mean; block(0,0) also writes constants ----
__global__ void k_sig(const float* __restrict__ x) {
    int t4 = blockIdx.x * blockDim.x + threadIdx.x;
    int b = blockIdx.y;

    if (blockIdx.x == 0 && b == 0) {
        // init constants (consumed by LATER kernels only)
        for (int i = threadIdx.x; i < 512; i += 256) {
            if (i < WIN) {
                double ang = -2.0 * PI_D * (double)i / 64.0;
                double sn, co;
                sincos(ang, &sn, &co);
                DS a = ds_from_d(co), bb = ds_from_d(sn);
                c_tw_re[i] = make_float2(a.hi, a.lo);
                c_tw_im[i] = make_float2(bb.hi, bb.lo);
                DS wd = ds_from_d(0.5 - 0.5 * cos(2.0 * PI_D * (double)i / 63.0));
                c_win[i] = make_float2(wd.hi, wd.lo);
            }
            if (i <= 16) {
                DS c = ds_from_d(2.0 * cos(2.0 * PI_D * (double)i / 32.0));
                c_c32[i] = make_float2(c.hi, c.lo);
            }
            if (i <= 10) {
                DS c = ds_from_d(1.0 / (double)(2 * i + 1));
                c_lnc[i] = make_float2(c.hi, c.lo);
            }
            if (i == 0) {
                DS l2 = ds_from_d(0.69314718055994530941723212145818);
                c_ln2 = make_float2(l2.hi, l2.lo);
                DS ep = ds_from_d(1e-8);
                c_eps = make_float2(ep.hi, ep.lo);
            }
            if (i <= NF) c_recip[i] = i ? 1.0 / (double)i : 0.0;
        }
    }

    if (t4 >= Ln / 4) return;
    const float4* p = (const float4*)(x + (size_t)b * Cn * Ln) + t4;
    float4 s = make_float4(0.f, 0.f, 0.f, 0.f);
    #pragma unroll
    for (int c = 0; c < Cn; ++c) {
        float4 v = p[(size_t)c * (Ln / 4)];
        ((float4*)g_x[b][c])[t4] = v;
        s.x += v.x; s.y += v.y; s.z += v.z; s.w += v.w;
    }
    s.x *= 0.03125f; s.y *= 0.03125f; s.z *= 0.03125f; s.w *= 0.03125f;
    ((float4*)g_sig[b])[t4] = s;
}

// ------------- 2) spectrogram features (DS fp32 DFT + DS log) --------------
__global__ void k_feats() {
    __shared__ float2 sv[WIN];
    __shared__ float2 twr[WIN], twi[WIN];
    __shared__ float  fr[WIN];
    __shared__ float  smean;
    int b = blockIdx.y, f = blockIdx.x, i = threadIdx.x;

    twr[i] = c_tw_re[i]; twi[i] = c_tw_im[i];
    fr[i] = g_sig[b][f * HOP + i];
    __syncthreads();

    if (i == 0) {
        float r[8];
        #pragma unroll
        for (int j = 0; j < 8; ++j) r[j] = fr[j];
        for (int o = 8; o < 64; o += 8) {
            #pragma unroll
            for (int j = 0; j < 8; ++j) r[j] += fr[o + j];
        }
        float s = ((r[0] + r[1]) + (r[2] + r[3])) + ((r[4] + r[5]) + (r[6] + r[7]));
        smean = s / 64.0f;
    }
    __syncthreads();

    {
        float d = fr[i] - smean;
        float2 w = c_win[i];
        float p = d * w.x;
        float e = fmaf(d, w.x, -p);
        e = fmaf(d, w.y, e);
        DS r = quick2(p, e);
        sv[i] = make_float2(r.hi, r.lo);
    }
    __syncthreads();

    if (i < ND) {
        DS re = {0.f, 0.f}, im = {0.f, 0.f};
        #pragma unroll 4
        for (int t = 0; t < WIN; ++t) {
            int m = (i * t) & 63;
            DS v  = {sv[t].x, sv[t].y};
            DS cr = {twr[m].x, twr[m].y};
            DS ci = {twi[m].x, twi[m].y};
            re = ds_add(re, ds_mul(v, cr));
            im = ds_add(im, ds_mul(v, ci));
        }
        DS p2 = ds_add(ds_mul(re, re), ds_mul(im, im));
        p2 = ds_add(p2, {c_eps.x, c_eps.y});
        DS lg = ds_log(p2);
        g_feats[b][f][i] = (double)lg.hi + (double)lg.lo;
    }
}

// --- 3) prefix sums (warp KS scan) + fused s2 scan (blockIdx.x == ND) -------
__global__ void k_prefix() {
    int d = blockIdx.x, b = blockIdx.y, lane = threadIdx.x;

    if (d == ND) {
        // s2[t] = prefix over t of (sum_d feats^2) — warp KS scan
        double carry = 0.0;
        if (lane == 0) g_s2[b][0] = 0.0;
        for (int base = 0; base < NF; base += 32) {
            int t = base + lane;
            double v = 0.0;
            if (t < NF) {
                const double* fr = g_feats[b][t];
                #pragma unroll
                for (int dd = 0; dd < ND; ++dd) v += fr[dd] * fr[dd];
            }
            #pragma unroll
            for (int o = 1; o < 32; o <<= 1) {
                double n1 = __shfl_up_sync(0xffffffffu, v, o);
                if (lane >= o) v += n1;
            }
            v += carry;
            if (t < NF) g_s2[b][t + 1] = v;
            carry = __shfl_sync(0xffffffffu, v, 31);
        }
        return;
    }

    double carry = 0.0, carry2 = 0.0;
    if (lane == 0) { g_cs[b][0][d] = 0.0; g_cs2[b][0][d] = 0.0; }
    for (int base = 0; base < NF; base += 32) {
        int t = base + lane;
        double v  = (t < NF) ? g_feats[b][t][d] : 0.0;
        double v2 = v * v;
        #pragma unroll
        for (int o = 1; o < 32; o <<= 1) {
            double n1 = __shfl_up_sync(0xffffffffu, v,  o);
            double n2 = __shfl_up_sync(0xffffffffu, v2, o);
            if (lane >= o) { v += n1; v2 += n2; }
        }
        v += carry; v2 += carry2;
        if (t < NF) {
            g_cs[b][t + 1][d]  = v;
            g_cs2[b][t + 1][d] = v2;
        }
        carry  = __shfl_sync(0xffffffffu, v, 31);
        carry2 = __shfl_sync(0xffffffffu, v2, 31);
    }
}

// ------ 4) PELT DP: R15 byte-identical (now ncu-profiled: 4th launch) -------
__global__ __launch_bounds__(256, 1) void k_pelt() {
    extern __shared__ double dyn[];
    double* s_cs    = dyn;                 // 16896 = 512*33
    double* s_s2    = dyn + 16896;         // 512
    double* s_Fc    = dyn + 17408;         // 512
    double* s_vals  = dyn + 17920;         // 512
    double* s_recip = dyn + 18432;         // 512
    short*  s_prev  = (short*)(dyn + 18944);        // 512 shorts
    short*  s_cands = s_prev + 512;                 // 514 shorts

    int b = blockIdx.x, tid = threadIdx.x;

    const double2* gc2 = (const double2*)g_cs[b];
    double2* sc2 = (double2*)s_cs;
    for (int i = tid; i < 8448; i += 256) sc2[i] = gc2[i];
    for (int i = tid; i < 512;  i += 256) {
        s_s2[i]    = g_s2[b][i];
        s_recip[i] = c_recip[i];
    }
    __syncthreads();
    if (tid >= 32) return;

    int lane = tid;
    int cg = lane >> 3;   // candidate slot within pass (0..3)
    int dl = lane & 7;    // dim lane (0..7)
    if (lane == 0) { s_Fc[0] = -PEN; s_cands[0] = 0; }
    int ncand = 1;
    __syncwarp();

    for (int t = 1; t <= NF; ++t) {
        const double* ct = s_cs + t * 33;
        double S2t = s_s2[t];
        double ctd[5];
        #pragma unroll
        for (int q = 0; q < 5; ++q) {
            int d = dl + q * 8;
            ctd[q] = (d < ND) ? ct[d] : 0.0;
        }

        if (ncand <= 4) {
            int j = cg;
            double val = 1e300;
            int c = 0;
            bool act = (j < ncand);
            if (act) c = s_cands[j];
            {
                const double* pc = s_cs + c * 33;
                double acc = 0.0;
                if (act) {
                    #pragma unroll
                    for (int q = 0; q < 5; ++q) {
                        int d = dl + q * 8;
                        if (d < ND) {
                            double su = ctd[q] - pc[d];
                            acc = fma(su, su, acc);
                        }
                    }
                }
                acc += __shfl_down_sync(0xffffffffu, acc, 4);
                acc += __shfl_down_sync(0xffffffffu, acc, 2);
                acc += __shfl_down_sync(0xffffffffu, acc, 1);
                if (act && dl == 0) {
                    double cost = (S2t - s_s2[c]) - acc * s_recip[t - c];
                    val = s_Fc[c] + cost + PEN;
                }
            }
            double v0 = __shfl_sync(0xffffffffu, val, 0);
            double v1 = __shfl_sync(0xffffffffu, val, 8);
            double v2 = __shfl_sync(0xffffffffu, val, 16);
            double v3 = __shfl_sync(0xffffffffu, val, 24);
            double bv = v0; int bj = 0;
            if (v1 < bv) { bv = v1; bj = 1; }
            if (v2 < bv) { bv = v2; bj = 2; }
            if (v3 < bv) { bv = v3; bj = 3; }
            if (lane == 0) { s_Fc[t] = bv; s_prev[t] = s_cands[bj]; }
            double thr = bv + PEN;
            double vm = (lane == 0) ? v0 : (lane == 1) ? v1 : (lane == 2) ? v2 : v3;
            bool keep = (lane < ncand) && (vm <= thr);
            unsigned msk = __ballot_sync(0xffffffffu, keep);
            short cj = (lane < ncand) ? s_cands[lane] : (short)0;
            int pos = __popc(msk & ((1u << lane) - 1u));
            __syncwarp();
            if (keep) s_cands[pos] = cj;
            int newn = __popc(msk);
            if (lane == 0) s_cands[newn] = (short)t;
            ncand = newn + 1;
            __syncwarp();
        } else {
            for (int base = 0; base < ncand; base += 4) {
                int j = base + cg;
                double acc = 0.0;
                int c = 0;
                bool act = (j < ncand);
                if (act) {
                    c = s_cands[j];
                    const double* pc = s_cs + c * 33;
                    #pragma unroll
                    for (int q = 0; q < 5; ++q) {
                        int d = dl + q * 8;
                        if (d < ND) {
                            double su = ctd[q] - pc[d];
                            acc = fma(su, su, acc);
                        }
                    }
                }
                acc += __shfl_down_sync(0xffffffffu, acc, 4);
                acc += __shfl_down_sync(0xffffffffu, acc, 2);
                acc += __shfl_down_sync(0xffffffffu, acc, 1);
                if (act && dl == 0) {
                    double cost = (S2t - s_s2[c]) - acc * s_recip[t - c];
                    s_vals[j] = s_Fc[c] + cost + PEN;
                }
            }
            __syncwarp();

            double bv = 1e300; int bj = 1 << 30;
            for (int j = lane; j < ncand; j += 32) {
                double v = s_vals[j];
                if (v < bv) { bv = v; bj = j; }
            }
            #pragma unroll
            for (int o = 16; o; o >>= 1) {
                double ov = __shfl_down_sync(0xffffffffu, bv, o);
                int    oj = __shfl_down_sync(0xffffffffu, bj, o);
                if (ov < bv || (ov == bv && oj < bj)) { bv = ov; bj = oj; }
            }
            bv = __shfl_sync(0xffffffffu, bv, 0);
            bj = __shfl_sync(0xffffffffu, bj, 0);
            if (lane == 0) { s_Fc[t] = bv; s_prev[t] = s_cands[bj]; }
            __syncwarp();

            double thr = bv + PEN;
            int newn = 0;
            for (int base = 0; base < ncand; base += 32) {
                int j = base + lane;
                short cj = 0; bool keep = false;
                if (j < ncand) { cj = s_cands[j]; keep = (s_vals[j] <= thr); }
                unsigned msk = __ballot_sync(0xffffffffu, keep);
                int pos = newn + __popc(msk & ((1u << lane) - 1u));
                __syncwarp();
                if (keep) s_cands[pos] = cj;
                newn += __popc(msk);
                __syncwarp();
            }
            if (lane == 0) s_cands[newn] = (short)t;
            ncand = newn + 1;
            __syncwarp();
        }
    }

    if (lane == 0) {
        short bps[NF + 1];
        int nb = 0, t = NF;
        while (t > 0) { bps[nb++] = (short)t; t = s_prev[t]; }
        int bnd[MAXSEG];
        int bc = 1; bnd[0] = 0;
        for (int ii = nb - 1; ii >= 1; --ii) {
            int k = bps[ii];
            int bpos = (k < NF) ? HOP * k : Ln;
            if (bpos > Ln) bpos = Ln;
            if (bpos - bnd[bc - 1] >= 8 && bc < MAXSEG - 1) bnd[bc++] = bpos;
        }
        if (Ln - bnd[bc - 1] < 8 && bc > 1) bc--;
        bnd[bc++] = Ln;
        int nseg = bc - 1;
        int off = 0;
        for (int s = 0; s < nseg; ++s) {
            g_seg_s[b][s]   = bnd[s];
            g_seg_e[b][s]   = bnd[s + 1];
            g_seg_off[b][s] = off;
            off += (bnd[s + 1] - bnd[s]) >> 1;
        }
        g_nseg[b] = nseg;
    }
}

// ---- 5) fused: fp32 pairwise mean + DS-Goertzel + stats (warp/segment) -----
__global__ void k_segspec() {
    __shared__ float buf[4][SEGBUF];
    int b = blockIdx.y;
    int wid = threadIdx.x >> 5, lane = threadIdx.x & 31;
    int nseg = g_nseg[b];
    int wg = blockIdx.x * 4 + wid;
    int nwarp = gridDim.x * 4;
    float* wb = buf[wid];

    for (int seg = wg; seg < nseg; seg += nwarp) {
        int s = g_seg_s[b][seg], e = g_seg_e[b][seg];
        int n = e - s, nf = n >> 1;
        const float* sp = &g_sig[b][s];

        float mean = 0.0f;
        if (lane == 0) mean = __fdiv_rn(np_pairwise_sum(sp, n), (float)n);
        mean = __shfl_sync(0xffffffffu, mean, 0);

        bool small = (n <= SEGBUF);
        __syncwarp();
        if (small)
            for (int t = lane; t < n; t += 32) wb[t] = sp[t] - mean;
        __syncwarp();

        double pw[16];
        int nb = 0;
        double tot = 0.0, mv = -1.0; int mk = 1 << 30;

        for (int k = lane + 1; k <= nf; k += 32) {
            DS coeff;
            if (n == 32) { float2 cc = c_c32[k]; coeff = {cc.x, cc.y}; }
            else coeff = ds_from_d(2.0 * cos(2.0 * PI_D * (double)k / (double)n));

            DS s1 = {0.f, 0.f}, s2 = {0.f, 0.f};
            if (small) {
                for (int t = 0; t < n; ++t) {
                    DS t1 = ds_add({wb[t], 0.f}, ds_neg(s2));
                    DS sn = ds_add(t1, ds_mul(coeff, s1));
                    s2 = s1; s1 = sn;
                }
            } else {
                for (int t = 0; t < n; ++t) {
                    float v = sp[t] - mean;
                    DS t1 = ds_add({v, 0.f}, ds_neg(s2));
                    DS sn = ds_add(t1, ds_mul(coeff, s1));
                    s2 = s1; s1 = sn;
                }
            }
            DS aa = ds_mul(s1, s1);
            DS bb = ds_mul(s2, s2);
            DS cc = ds_mul(ds_mul(coeff, s1), s2);
            DS pp = ds_add(ds_add(aa, bb), ds_neg(cc));
            double pwv = (double)pp.hi + (double)pp.lo;
            if (pwv < 0.0) pwv = 0.0;
            if (small) pw[nb] = pwv;
            else g_spec[b][g_seg_off[b][seg] + (k - 1)] = pwv;
            ++nb;
            tot += pwv;
            if (pwv > mv) { mv = pwv; mk = k; }
        }
        __syncwarp();

        #pragma unroll
        for (int o = 16; o; o >>= 1) {
            tot += __shfl_down_sync(0xffffffffu, tot, o);
            double ov = __shfl_down_sync(0xffffffffu, mv, o);
            int    ok = __shfl_down_sync(0xffffffffu, mk, o);
            if (ov > mv || (ov == mv && ok < mk)) { mv = ov; mk = ok; }
        }
        tot = __shfl_sync(0xffffffffu, tot, 0);
        mk  = __shfl_sync(0xffffffffu, mk, 0);

        double dpv, bwvv;
        if (tot <= 0.0 || nf < 1) {
            dpv = (double)n; bwvv = 0.0;
        } else {
            double invtot = 1.0 / tot, invnf = 1.0 / (double)nf;
            double cacc = 0.0;
            { int i2 = 0;
              for (int k = lane + 1; k <= nf; k += 32) {
                  double v = small ? pw[i2++] : g_spec[b][g_seg_off[b][seg] + (k - 1)];
                  cacc += (v * invtot) * ((double)k * invnf);
              } }
            #pragma unroll
            for (int o = 16; o; o >>= 1) cacc += __shfl_down_sync(0xffffffffu, cacc, o);
            cacc = __shfl_sync(0xffffffffu, cacc, 0);

            double bacc = 0.0;
            { int i2 = 0;
              for (int k = lane + 1; k <= nf; k += 32) {
                  double v = small ? pw[i2++] : g_spec[b][g_seg_off[b][seg] + (k - 1)];
                  double fd = (double)k * invnf - cacc;
                  bacc += (v * invtot) * fd * fd;
              } }
            #pragma unroll
            for (int o = 16; o; o >>= 1) bacc += __shfl_down_sync(0xffffffffu, bacc, o);
            bacc = __shfl_sync(0xffffffffu, bacc, 0);

            dpv  = (double)n / (double)mk;
            bwvv = sqrt(bacc);
        }

        if (lane == 0) {
            g_dp[b][seg]  = dpv;
            g_bwv[b][seg] = bwvv;
            double raw = dpv / (1.0 + bwvv);
            double r = rint(raw * 0.5);
            int pl = (int)(2.0 * r);
            pl = pl < 8 ? 8 : (pl > 64 ? 64 : pl);
            g_pl[b][seg] = pl;
        }
        __syncwarp();
    }
}

// --------------- 6) token build (scan) + ntok output -----------------------
__global__ void k_tokens(float* __restrict__ o_ntok) {
    __shared__ int cnt[512];
    int b = blockIdx.x, tid = threadIdx.x;
    int nseg = g_nseg[b];
    int c = 0, s = 0, e = 0, pl = 8;
    if (tid < nseg) {
        s = g_seg_s[b][tid]; e = g_seg_e[b][tid]; pl = g_pl[b][tid];
        int len = e - s;
        int nfl = len / pl;
        c = nfl + ((len - nfl * pl) > 0 ? 1 : 0);
    }
    cnt[tid] = c;
    __syncthreads();
    for (int o = 1; o < 512; o <<= 1) {
        int v = cnt[tid];
        if (tid >= o) v += cnt[tid - o];
        __syncthreads();
        cnt[tid] = v;
        __syncthreads();
    }
    if (tid < nseg) {
        int off = cnt[tid] - c;
        int len = e - s;
        int nfl = len / pl;
        for (int i = 0; i < nfl; ++i) {
            g_tok_s[b][off + i]   = s + i * pl;
            g_tok_e[b][off + i]   = s + (i + 1) * pl;
            g_tok_seg[b][off + i] = tid;
        }
        if (nfl * pl < len) {
            g_tok_s[b][off + nfl]   = s + nfl * pl;
            g_tok_e[b][off + nfl]   = e;
            g_tok_seg[b][off + nfl] = tid;
        }
    }
    if (tid == 0) {
        g_ntok[b] = cnt[511];
        o_ntok[b] = (float)cnt[511];
    }
}

// -------------------------- 7a) scalar outputs ------------------------------
__global__ void k_scalars(float* __restrict__ o_mask, float* __restrict__ o_start,
                          float* __restrict__ o_end, float* __restrict__ o_center,
                          float* __restrict__ o_span, float* __restrict__ o_regime,
                          int mt) {
    int i = blockIdx.x * blockDim.x + threadIdx.x;
    int b = blockIdx.y;
    if (i >= mt) return;
    float m = 0.f, st = 0.f, en = 0.f, ce = 0.f, sp = 0.f, r0 = 0.f, r1 = 0.f, r2 = 0.f;
    if (i < g_ntok[b]) {
        int s = g_tok_s[b][i], e = g_tok_e[b][i], seg = g_tok_seg[b][i];
        m = 1.0f;
        st = (float)s; en = (float)e;
        ce = ((float)s + (float)e - 1.0f) * 0.5f / 16383.0f;
        sp = (float)(e - s) / 16384.0f;
        int sl = g_seg_e[b][seg] - g_seg_s[b][seg];
        r0 = (float)(g_dp[b][seg] / 16384.0);
        r1 = (float)g_bwv[b][seg];
        r2 = (float)((double)sl / 16384.0);
    }
    size_t idx = (size_t)b * mt + i;
    o_mask[idx] = m; o_start[idx] = st; o_end[idx] = en;
    o_center[idx] = ce; o_span[idx] = sp;
    o_regime[idx * 3 + 0] = r0;
    o_regime[idx * 3 + 1] = r1;
    o_regime[idx * 3 + 2] = r2;
}

// ---- 7b) patches (gather + lerp) g_x -> d_out, float4 stores ---------------
__global__ __launch_bounds__(256) void k_patches(float* __restrict__ o_patch, int mt) {
    int b = blockIdx.y;
    int tok = blockIdx.x * 2 + (threadIdx.x >> 7);
    int r = threadIdx.x & 127;
    int c = r >> 2, q = r & 3;
    if (tok >= mt) return;

    size_t obase = (((size_t)b * mt + tok) * Cn + c) * ANCH + q * 4;
    float4 v = make_float4(0.f, 0.f, 0.f, 0.f);
    if (tok < g_ntok[b]) {
        int s = g_tok_s[b][tok], e = g_tok_e[b][tok];
        int il = e - s;
        float scale = (float)il / 16.0f;
        const float* row = g_x[b][c] + s;
        float o[4];
        #pragma unroll
        for (int jj = 0; jj < 4; ++jj) {
            int j = q * 4 + jj;
            float coord = ((float)j + 0.5f) * scale - 0.5f;
            coord = fminf(fmaxf(coord, 0.0f), (float)(il - 1));
            int l = (int)floorf(coord);
            int h = min(l + 1, il - 1);
            float w = coord - (float)l;
            o[jj] = row[l] * (1.0f - w) + row[h] * w;
        }
        v = make_float4(o[0], o[1], o[2], o[3]);
    }
    *(float4*)(o_patch + obase) = v;
}

// --------------------------------- launch -----------------------------------
extern "C" void kernel_launch(void* const* d_in, const int* in_sizes, int n_in,
                              void* d_out, int out_size) {
    const float* x = (const float*)d_in[0];
    float* out = (float*)d_out;

    long long mt_ll = ((long long)out_size - Bn) / (16384 + 5 * Bn + 3 * Bn);
    if (mt_ll < 1) mt_ll = 1;
    int mt = (int)mt_ll;

    float* o_patch  = out;
    float* o_mask   = out + (size_t)Bn * mt * Cn * ANCH;
    float* o_start  = o_mask   + (size_t)Bn * mt;
    float* o_end    = o_start  + (size_t)Bn * mt;
    float* o_center = o_end    + (size_t)Bn * mt;
    float* o_span   = o_center + (size_t)Bn * mt;
    float* o_regime = o_span   + (size_t)Bn * mt;
    float* o_ntok   = o_regime + (size_t)Bn * mt * 3;

    static bool attr_done = false;
    if (!attr_done) {
        cudaFuncSetAttribute(k_pelt, cudaFuncAttributeMaxDynamicSharedMemorySize,
                             (int)PELT_SMEM);
        attr_done = true;
    }

    k_sig<<<dim3(16, Bn), 256>>>(x);                 // 1 (incl. constant init)
    k_feats<<<dim3(NF, Bn), WIN>>>();                // 2
    k_prefix<<<dim3(ND + 1, Bn), 32>>>();            // 3 (incl. fused s2)
    k_pelt<<<Bn, 256, PELT_SMEM>>>();                // 4  <-- ncu-profiled
    k_segspec<<<dim3(128, Bn), 128>>>();             // 5
    k_tokens<<<Bn, 512>>>(o_ntok);                   // 6
    k_scalars<<<dim3((mt + 255) / 256, Bn), 256>>>(o_mask, o_start, o_end,
                                                   o_center, o_span, o_regime, mt); // 7
    k_patches<<<dim3((mt + 1) / 2, Bn), 256>>>(o_patch, mt);                        // 8
}